// round 1
// baseline (speedup 1.0000x reference)
#include <cuda_runtime.h>
#include <math.h>

#define B_  8
#define H_  16
#define S_  1024
#define DK_ 64
#define DM_ 1024
#define M_  (B_*S_)   // 8192

// scratch (allocation-free rule: __device__ globals)
__device__ float g_qh[B_*H_*S_*DK_];
__device__ float g_kh[B_*H_*S_*DK_];
__device__ float g_vh[B_*H_*S_*DK_];
__device__ float g_oc[M_*DM_];

// ---------------------------------------------------------------------------
// GEMM: C[M x N] = X[M x K] * W^T  (W stored [N x K] row-major) + bias[N]
// M=8192, N=1024, K=1024 fixed. Tile 128x128, BK=8, 256 thr, 8x8 per thread.
// bhsd_mode=1: scatter output to [b,h,s,dk] layout; 0: plain row-major.
// ---------------------------------------------------------------------------
#define BM 128
#define BN 128
#define BKK 8

__global__ __launch_bounds__(256) void gemm_xwt(
    const float* __restrict__ X, const float* __restrict__ W,
    const float* __restrict__ bias, float* __restrict__ out, int bhsd_mode)
{
    __shared__ float As[BKK][BM];
    __shared__ float Bs[BKK][BN];
    const int tid = threadIdx.x;
    const int bm = blockIdx.y * BM;
    const int bn = blockIdx.x * BN;
    const int lr = tid >> 1;        // 0..127 : load row
    const int lk = (tid & 1) * 4;   // 0 or 4 : k offset
    const int tm = tid >> 4;        // 0..15
    const int tn = tid & 15;        // 0..15

    float acc[8][8];
    #pragma unroll
    for (int i = 0; i < 8; i++)
        #pragma unroll
        for (int j = 0; j < 8; j++) acc[i][j] = 0.0f;

    const float* Xp = X + (size_t)(bm + lr) * 1024 + lk;
    const float* Wp = W + (size_t)(bn + lr) * 1024 + lk;

    for (int k0 = 0; k0 < 1024; k0 += BKK) {
        float4 a = *(const float4*)(Xp + k0);
        float4 b = *(const float4*)(Wp + k0);
        As[lk+0][lr] = a.x; As[lk+1][lr] = a.y; As[lk+2][lr] = a.z; As[lk+3][lr] = a.w;
        Bs[lk+0][lr] = b.x; Bs[lk+1][lr] = b.y; Bs[lk+2][lr] = b.z; Bs[lk+3][lr] = b.w;
        __syncthreads();
        #pragma unroll
        for (int k = 0; k < BKK; k++) {
            float ar[8], br[8];
            *(float4*)&ar[0] = *(const float4*)&As[k][tm*4];
            *(float4*)&ar[4] = *(const float4*)&As[k][64 + tm*4];
            *(float4*)&br[0] = *(const float4*)&Bs[k][tn*4];
            *(float4*)&br[4] = *(const float4*)&Bs[k][64 + tn*4];
            #pragma unroll
            for (int i = 0; i < 8; i++)
                #pragma unroll
                for (int j = 0; j < 8; j++)
                    acc[i][j] += ar[i] * br[j];
        }
        __syncthreads();
    }

    #pragma unroll
    for (int i = 0; i < 8; i++) {
        int grow = bm + ((i < 4) ? (tm*4 + i) : (64 + tm*4 + (i - 4)));
        #pragma unroll
        for (int j = 0; j < 8; j++) {
            int gcol = bn + ((j < 4) ? (tn*4 + j) : (64 + tn*4 + (j - 4)));
            float val = acc[i][j] + bias[gcol];
            if (bhsd_mode) {
                int bb = grow >> 10, ss = grow & 1023;
                int hh = gcol >> 6,  dk = gcol & 63;
                out[(((size_t)(bb*H_ + hh))*S_ + ss)*DK_ + dk] = val;
            } else {
                out[(size_t)grow * DM_ + gcol] = val;
            }
        }
    }
}

// ---------------------------------------------------------------------------
// Flash-style attention per (b,h). Block = 256 thr = 8 warps, 4 q-rows/warp
// (32 q-rows per block). Key/value tiles of 64 rows in padded smem.
// Q is pre-scaled by 1/temper so s IS the reference "scores" value, and the
// faithful mask (score==0 -> -inf) is applied on it.
// ---------------------------------------------------------------------------
__global__ __launch_bounds__(256) void attn_kernel(
    const float* __restrict__ qh, const float* __restrict__ kh,
    const float* __restrict__ vh, float* __restrict__ ocat)
{
    extern __shared__ float sm[];
    float* Ks = sm;                // [64][65]
    float* Vs = Ks + 64*65;        // [64][65]
    float* Qs = Vs + 64*65;        // [32][64]
    float* Ps = Qs + 32*64;        // [32][64]  (8 warps * 4 rows)

    const int tid  = threadIdx.x;
    const int warp = tid >> 5, lane = tid & 31;
    const int bh   = blockIdx.y;
    const int b    = bh >> 4, h = bh & 15;
    const int row0 = blockIdx.x * 32;

    const float* Q  = qh + (size_t)bh * S_ * DK_;
    const float* Kp = kh + (size_t)bh * S_ * DK_;
    const float* Vp = vh + (size_t)bh * S_ * DK_;

    // load Q tile (pre-scaled by 1/8 = 1/sqrt(64))
    for (int t = tid; t < 32*16; t += 256) {
        int r = t >> 4, c = (t & 15) * 4;
        float4 qv = *(const float4*)&Q[(size_t)(row0 + r)*DK_ + c];
        Qs[r*64 + c + 0] = qv.x * 0.125f;
        Qs[r*64 + c + 1] = qv.y * 0.125f;
        Qs[r*64 + c + 2] = qv.z * 0.125f;
        Qs[r*64 + c + 3] = qv.w * 0.125f;
    }

    float m[4], l[4], o0[4], o1[4];
    #pragma unroll
    for (int r = 0; r < 4; r++) { m[r] = -INFINITY; l[r] = 0.0f; o0[r] = 0.0f; o1[r] = 0.0f; }
    __syncthreads();

    for (int j0 = 0; j0 < S_; j0 += 64) {
        // load K/V tiles
        for (int t = tid; t < 64*16; t += 256) {
            int r = t >> 4, c = (t & 15) * 4;
            float4 kv = *(const float4*)&Kp[(size_t)(j0 + r)*DK_ + c];
            Ks[r*65 + c + 0] = kv.x; Ks[r*65 + c + 1] = kv.y;
            Ks[r*65 + c + 2] = kv.z; Ks[r*65 + c + 3] = kv.w;
            float4 vv = *(const float4*)&Vp[(size_t)(j0 + r)*DK_ + c];
            Vs[r*65 + c + 0] = vv.x; Vs[r*65 + c + 1] = vv.y;
            Vs[r*65 + c + 2] = vv.z; Vs[r*65 + c + 3] = vv.w;
        }
        __syncthreads();

        // scores: each lane -> keys (lane) and (lane+32), 4 rows
        float s0[4], s1[4];
        #pragma unroll
        for (int r = 0; r < 4; r++) { s0[r] = 0.0f; s1[r] = 0.0f; }
        #pragma unroll
        for (int d = 0; d < 64; d++) {
            float k0v = Ks[lane*65 + d];
            float k1v = Ks[(lane + 32)*65 + d];
            #pragma unroll
            for (int r = 0; r < 4; r++) {
                float qd = Qs[(warp*4 + r)*64 + d];
                s0[r] += qd * k0v;
                s1[r] += qd * k1v;
            }
        }

        // faithful mask + online softmax
        #pragma unroll
        for (int r = 0; r < 4; r++) {
            float a = s0[r], c = s1[r];
            if (a == 0.0f) a = -INFINITY;
            if (c == 0.0f) c = -INFINITY;
            float mx = fmaxf(a, c);
            #pragma unroll
            for (int off = 16; off; off >>= 1)
                mx = fmaxf(mx, __shfl_xor_sync(0xffffffffu, mx, off));
            float mnew = fmaxf(fmaxf(m[r], mx), -1e30f);
            float p0 = __expf(a - mnew);
            float p1 = __expf(c - mnew);
            float alpha = __expf(m[r] - mnew);
            float ps = p0 + p1;
            #pragma unroll
            for (int off = 16; off; off >>= 1)
                ps += __shfl_xor_sync(0xffffffffu, ps, off);
            l[r] = l[r]*alpha + ps;
            o0[r] *= alpha; o1[r] *= alpha;
            m[r] = mnew;
            Ps[(warp*4 + r)*64 + lane]      = p0;
            Ps[(warp*4 + r)*64 + lane + 32] = p1;
        }
        __syncwarp();

        // O += P @ V  (lane owns dims lane and lane+32)
        #pragma unroll
        for (int j = 0; j < 64; j++) {
            float v0 = Vs[j*65 + lane];
            float v1 = Vs[j*65 + lane + 32];
            #pragma unroll
            for (int r = 0; r < 4; r++) {
                float p = Ps[(warp*4 + r)*64 + j];
                o0[r] += p * v0;
                o1[r] += p * v1;
            }
        }
        __syncthreads();
    }

    // write normalized output in concat layout [b, s, h*64 + d]
    #pragma unroll
    for (int r = 0; r < 4; r++) {
        int grow = row0 + warp*4 + r;
        float inv = 1.0f / l[r];
        size_t base = ((size_t)b * S_ + grow) * DM_ + h * DK_;
        ocat[base + lane]      = o0[r] * inv;
        ocat[base + lane + 32] = o1[r] * inv;
    }
}

// ---------------------------------------------------------------------------

extern "C" void kernel_launch(void* const* d_in, const int* in_sizes, int n_in,
                              void* d_out, int out_size)
{
    const float* q  = (const float*)d_in[0];
    const float* k  = (const float*)d_in[1];
    const float* v  = (const float*)d_in[2];
    const float* Wq = (const float*)d_in[3];
    const float* bq = (const float*)d_in[4];
    const float* Wk = (const float*)d_in[5];
    const float* bk = (const float*)d_in[6];
    const float* Wv = (const float*)d_in[7];
    const float* bv = (const float*)d_in[8];
    const float* Wf = (const float*)d_in[9];
    const float* bf = (const float*)d_in[10];
    float* out = (float*)d_out;

    float *qh, *kh, *vh, *oc;
    cudaGetSymbolAddress((void**)&qh, g_qh);
    cudaGetSymbolAddress((void**)&kh, g_kh);
    cudaGetSymbolAddress((void**)&vh, g_vh);
    cudaGetSymbolAddress((void**)&oc, g_oc);

    dim3 gg(DM_/BN, M_/BM);   // (8, 64)
    gemm_xwt<<<gg, 256>>>(q, Wq, bq, qh, 1);
    gemm_xwt<<<gg, 256>>>(k, Wk, bk, kh, 1);
    gemm_xwt<<<gg, 256>>>(v, Wv, bv, vh, 1);

    int smem_bytes = (64*65*2 + 32*64 + 32*64) * (int)sizeof(float);  // 49664
    cudaFuncSetAttribute(attn_kernel, cudaFuncAttributeMaxDynamicSharedMemorySize, smem_bytes);
    attn_kernel<<<dim3(S_/32, B_*H_), 256, smem_bytes>>>(qh, kh, vh, oc);

    gemm_xwt<<<gg, 256>>>(oc, Wf, bf, out, 0);
}

// round 4
// speedup vs baseline: 1.5405x; 1.5405x over previous
#include <cuda_runtime.h>
#include <cuda_bf16.h>
#include <math.h>
#include <stdint.h>

#define B_  8
#define H_  16
#define S_  1024
#define DK_ 64
#define DM_ 1024
#define M_  (B_*S_)          // 8192
#define NE  (M_*DM_)         // 8M activation elems
#define NW  (DM_*DM_)        // 1M weight elems

// ---- scratch (allocation-free rule: __device__ globals) --------------------
__device__ float g_qh[NE], g_kh[NE], g_vh[NE];
__device__ __nv_bfloat16 g_qhi[NE], g_qlo[NE];
__device__ __nv_bfloat16 g_khi[NE], g_klo[NE];
__device__ __nv_bfloat16 g_vhi[NE], g_vlo[NE];
__device__ __nv_bfloat16 g_ochi[NE], g_oclo[NE];
__device__ __nv_bfloat16 g_wqhi[NW], g_wqlo[NW];
__device__ __nv_bfloat16 g_wkhi[NW], g_wklo[NW];
__device__ __nv_bfloat16 g_wvhi[NW], g_wvlo[NW];
__device__ __nv_bfloat16 g_wfhi[NW], g_wflo[NW];

// ---- helpers ---------------------------------------------------------------
__device__ __forceinline__ uint32_t smem_u32(const void* p) {
    uint32_t a;
    asm("{ .reg .u64 t; cvta.to.shared.u64 t, %1; cvt.u32.u64 %0, t; }"
        : "=r"(a) : "l"(p));
    return a;
}

__device__ __forceinline__ void cp16(uint32_t dst, const void* src) {
    asm volatile("cp.async.cg.shared.global [%0], [%1], 16;"
                 :: "r"(dst), "l"(src));
}

__device__ __forceinline__ void ldsm4(uint32_t* r, uint32_t addr) {
    asm volatile("ldmatrix.sync.aligned.m8n8.x4.shared.b16 {%0,%1,%2,%3}, [%4];"
                 : "=r"(r[0]), "=r"(r[1]), "=r"(r[2]), "=r"(r[3]) : "r"(addr));
}

__device__ __forceinline__ void mma_bf16(float* d, const uint32_t* a, const uint32_t* b) {
    asm volatile(
        "mma.sync.aligned.m16n8k16.row.col.f32.bf16.bf16.f32 "
        "{%0,%1,%2,%3}, {%4,%5,%6,%7}, {%8,%9}, {%0,%1,%2,%3};"
        : "+f"(d[0]), "+f"(d[1]), "+f"(d[2]), "+f"(d[3])
        : "r"(a[0]), "r"(a[1]), "r"(a[2]), "r"(a[3]), "r"(b[0]), "r"(b[1]));
}

// ---------------------------------------------------------------------------
// fp32 -> (bf16 hi, bf16 lo) splitter
// ---------------------------------------------------------------------------
__global__ __launch_bounds__(256) void split_fp32(
    const float* __restrict__ x, __nv_bfloat16* __restrict__ hi,
    __nv_bfloat16* __restrict__ lo, int n4)
{
    int i = blockIdx.x * blockDim.x + threadIdx.x;
    if (i >= n4) return;
    float4 v = ((const float4*)x)[i];
    __nv_bfloat16 h0 = __float2bfloat16(v.x);
    __nv_bfloat16 h1 = __float2bfloat16(v.y);
    __nv_bfloat16 h2 = __float2bfloat16(v.z);
    __nv_bfloat16 h3 = __float2bfloat16(v.w);
    __nv_bfloat16 l0 = __float2bfloat16(v.x - __bfloat162float(h0));
    __nv_bfloat16 l1 = __float2bfloat16(v.y - __bfloat162float(h1));
    __nv_bfloat16 l2 = __float2bfloat16(v.z - __bfloat162float(h2));
    __nv_bfloat16 l3 = __float2bfloat16(v.w - __bfloat162float(h3));
    ((__nv_bfloat162*)hi)[2*i]     = __halves2bfloat162(h0, h1);
    ((__nv_bfloat162*)hi)[2*i + 1] = __halves2bfloat162(h2, h3);
    ((__nv_bfloat162*)lo)[2*i]     = __halves2bfloat162(l0, l1);
    ((__nv_bfloat162*)lo)[2*i + 1] = __halves2bfloat162(l2, l3);
}

// ---------------------------------------------------------------------------
// GEMM via mma.sync (bf16, fp32 acc):
//   C[8192 x 1024] = A[8192 x 1024] * B^T (+ bias), 3-term hi/lo emulation.
// 128x128 C-tile / CTA; BK=32; 8 warps (4 M x 2 N); warp tile 32x64.
// Smem: 2 stages x 4 tiles (Ahi,Alo,Bhi,Blo) of 128 rows x 80B (64B data+pad).
// bhsd_mode=1 scatters the output to [b,h,s,dk].
// ---------------------------------------------------------------------------
#define TS_    10240          // one tile: 128 rows * 80 B
#define STAGE_ (4*TS_)        // 40960

__global__ __launch_bounds__(256, 2) void gemm_mma(
    const __nv_bfloat16* __restrict__ Ahi, const __nv_bfloat16* __restrict__ Alo,
    const __nv_bfloat16* __restrict__ Bhi, const __nv_bfloat16* __restrict__ Blo,
    const float* __restrict__ bias, float* __restrict__ out, int bhsd_mode)
{
    extern __shared__ __align__(128) char smem[];
    const uint32_t sb = smem_u32(smem);
    const int tid = threadIdx.x, warp = tid >> 5, lane = tid & 31;
    const int wm = warp & 3, wn = warp >> 2;
    const int bm = blockIdx.y * 128, bn = blockIdx.x * 128;

    const char* src[4] = {
        (const char*)Ahi + (size_t)bm * 2048,
        (const char*)Alo + (size_t)bm * 2048,
        (const char*)Bhi + (size_t)bn * 2048,
        (const char*)Blo + (size_t)bn * 2048 };

    float acc[2][8][4];
    #pragma unroll
    for (int mi = 0; mi < 2; ++mi)
        #pragma unroll
        for (int nj = 0; nj < 8; ++nj)
            #pragma unroll
            for (int e = 0; e < 4; ++e) acc[mi][nj][e] = 0.0f;

    // ldmatrix per-lane offsets (80B padded rows -> conflict-free)
    const uint32_t offA = (uint32_t)((lane & 15) * 80 + (lane >> 4) * 16);
    const uint32_t offB = (uint32_t)(((((lane >> 4) & 1) * 8) + (lane & 7)) * 80
                                     + ((lane >> 3) & 1) * 16);

    const int lrow = tid >> 2;            // 0..63  (with it-offset covers 128)
    const int lseg = (tid & 3) * 16;      // byte segment within 64B row-chunk

    // ---- prologue: stage chunk 0 ----
    {
        #pragma unroll
        for (int t = 0; t < 4; ++t)
            #pragma unroll
            for (int it = 0; it < 2; ++it) {
                int row = lrow + it * 64;
                cp16(sb + t * TS_ + row * 80 + lseg,
                     src[t] + (size_t)row * 2048 + lseg);
            }
        asm volatile("cp.async.commit_group;");
    }

    for (int chunk = 0; chunk < 32; ++chunk) {
        if (chunk < 31) {
            const uint32_t stg = ((chunk + 1) & 1) * STAGE_;
            const int kb = (chunk + 1) * 64;
            #pragma unroll
            for (int t = 0; t < 4; ++t)
                #pragma unroll
                for (int it = 0; it < 2; ++it) {
                    int row = lrow + it * 64;
                    cp16(sb + stg + t * TS_ + row * 80 + lseg,
                         src[t] + (size_t)row * 2048 + kb + lseg);
                }
            asm volatile("cp.async.commit_group;");
            asm volatile("cp.async.wait_group 1;");
        } else {
            asm volatile("cp.async.wait_group 0;");
        }
        __syncthreads();

        const uint32_t stage = sb + (chunk & 1) * STAGE_;
        #pragma unroll
        for (int term = 0; term < 3; ++term) {
            const int ta = (term == 2) ? 1 : 0;   // Ahi,Ahi,Alo
            const int tb = (term == 1) ? 3 : 2;   // Bhi,Blo,Bhi
            const uint32_t aBase = stage + ta * TS_ + wm * 32 * 80 + offA;
            const uint32_t bBase = stage + tb * TS_ + wn * 64 * 80 + offB;
            #pragma unroll
            for (int ks = 0; ks < 2; ++ks) {
                uint32_t ra[2][4], rb[4][4];
                ldsm4(ra[0], aBase + ks * 32);
                ldsm4(ra[1], aBase + 16 * 80 + ks * 32);
                #pragma unroll
                for (int j = 0; j < 4; ++j)
                    ldsm4(rb[j], bBase + j * 16 * 80 + ks * 32);
                #pragma unroll
                for (int mi = 0; mi < 2; ++mi)
                    #pragma unroll
                    for (int nj = 0; nj < 8; ++nj)
                        mma_bf16(acc[mi][nj], ra[mi], &rb[nj >> 1][(nj & 1) * 2]);
            }
        }
        __syncthreads();
    }

    // ---- epilogue ----
    const int r0 = bm + wm * 32 + (lane >> 2);
    const int c0 = bn + wn * 64 + (lane & 3) * 2;
    #pragma unroll
    for (int mi = 0; mi < 2; ++mi) {
        #pragma unroll
        for (int nj = 0; nj < 8; ++nj) {
            const int gc = c0 + nj * 8;
            const float bx = bias[gc], by = bias[gc + 1];
            #pragma unroll
            for (int half = 0; half < 2; ++half) {
                const int row = r0 + mi * 16 + half * 8;
                float2 v;
                v.x = acc[mi][nj][half * 2 + 0] + bx;
                v.y = acc[mi][nj][half * 2 + 1] + by;
                if (bhsd_mode) {
                    int bb = row >> 10, ss = row & 1023;
                    int hh = gc >> 6, dk = gc & 63;
                    *(float2*)&out[(((size_t)(bb * H_ + hh)) * S_ + ss) * DK_ + dk] = v;
                } else {
                    *(float2*)&out[(size_t)row * DM_ + gc] = v;
                }
            }
        }
    }
}

// ---------------------------------------------------------------------------
// Flash-style fp32 attention per (b,h). 256 thr, 4 q-rows/warp, 64-row K/V
// tiles. Writes output directly as bf16 hi/lo for the final GEMM.
// ---------------------------------------------------------------------------
__global__ __launch_bounds__(256) void attn_kernel(
    const float* __restrict__ qh, const float* __restrict__ kh,
    const float* __restrict__ vh,
    __nv_bfloat16* __restrict__ ochi, __nv_bfloat16* __restrict__ oclo)
{
    extern __shared__ float sm[];
    float* Ks = sm;                // [64][65]
    float* Vs = Ks + 64*65;        // [64][65]
    float* Qs = Vs + 64*65;        // [32][64]
    float* Ps = Qs + 32*64;        // [32][64]

    const int tid  = threadIdx.x;
    const int warp = tid >> 5, lane = tid & 31;
    const int bh   = blockIdx.y;
    const int b    = bh >> 4, h = bh & 15;
    const int row0 = blockIdx.x * 32;

    const float* Q  = qh + (size_t)bh * S_ * DK_;
    const float* Kp = kh + (size_t)bh * S_ * DK_;
    const float* Vp = vh + (size_t)bh * S_ * DK_;

    for (int t = tid; t < 32*16; t += 256) {
        int r = t >> 4, c = (t & 15) * 4;
        float4 qv = *(const float4*)&Q[(size_t)(row0 + r)*DK_ + c];
        Qs[r*64 + c + 0] = qv.x * 0.125f;
        Qs[r*64 + c + 1] = qv.y * 0.125f;
        Qs[r*64 + c + 2] = qv.z * 0.125f;
        Qs[r*64 + c + 3] = qv.w * 0.125f;
    }

    float m[4], l[4], o0[4], o1[4];
    #pragma unroll
    for (int r = 0; r < 4; r++) { m[r] = -INFINITY; l[r] = 0.0f; o0[r] = 0.0f; o1[r] = 0.0f; }
    __syncthreads();

    for (int j0 = 0; j0 < S_; j0 += 64) {
        for (int t = tid; t < 64*16; t += 256) {
            int r = t >> 4, c = (t & 15) * 4;
            float4 kv = *(const float4*)&Kp[(size_t)(j0 + r)*DK_ + c];
            Ks[r*65 + c + 0] = kv.x; Ks[r*65 + c + 1] = kv.y;
            Ks[r*65 + c + 2] = kv.z; Ks[r*65 + c + 3] = kv.w;
            float4 vv = *(const float4*)&Vp[(size_t)(j0 + r)*DK_ + c];
            Vs[r*65 + c + 0] = vv.x; Vs[r*65 + c + 1] = vv.y;
            Vs[r*65 + c + 2] = vv.z; Vs[r*65 + c + 3] = vv.w;
        }
        __syncthreads();

        float s0[4], s1[4];
        #pragma unroll
        for (int r = 0; r < 4; r++) { s0[r] = 0.0f; s1[r] = 0.0f; }
        #pragma unroll
        for (int d = 0; d < 64; d++) {
            float k0v = Ks[lane*65 + d];
            float k1v = Ks[(lane + 32)*65 + d];
            #pragma unroll
            for (int r = 0; r < 4; r++) {
                float qd = Qs[(warp*4 + r)*64 + d];
                s0[r] += qd * k0v;
                s1[r] += qd * k1v;
            }
        }

        #pragma unroll
        for (int r = 0; r < 4; r++) {
            float a = s0[r], c = s1[r];
            if (a == 0.0f) a = -INFINITY;
            if (c == 0.0f) c = -INFINITY;
            float mx = fmaxf(a, c);
            #pragma unroll
            for (int off = 16; off; off >>= 1)
                mx = fmaxf(mx, __shfl_xor_sync(0xffffffffu, mx, off));
            float mnew = fmaxf(fmaxf(m[r], mx), -1e30f);
            float p0 = __expf(a - mnew);
            float p1 = __expf(c - mnew);
            float alpha = __expf(m[r] - mnew);
            float ps = p0 + p1;
            #pragma unroll
            for (int off = 16; off; off >>= 1)
                ps += __shfl_xor_sync(0xffffffffu, ps, off);
            l[r] = l[r]*alpha + ps;
            o0[r] *= alpha; o1[r] *= alpha;
            m[r] = mnew;
            Ps[(warp*4 + r)*64 + lane]      = p0;
            Ps[(warp*4 + r)*64 + lane + 32] = p1;
        }
        __syncwarp();

        #pragma unroll
        for (int j = 0; j < 64; j++) {
            float v0 = Vs[j*65 + lane];
            float v1 = Vs[j*65 + lane + 32];
            #pragma unroll
            for (int r = 0; r < 4; r++) {
                float p = Ps[(warp*4 + r)*64 + j];
                o0[r] += p * v0;
                o1[r] += p * v1;
            }
        }
        __syncthreads();
    }

    #pragma unroll
    for (int r = 0; r < 4; r++) {
        int grow = row0 + warp*4 + r;
        float inv = 1.0f / l[r];
        size_t base = ((size_t)b * S_ + grow) * DM_ + h * DK_;
        float v0 = o0[r] * inv;
        float v1 = o1[r] * inv;
        __nv_bfloat16 h0 = __float2bfloat16(v0);
        __nv_bfloat16 h1 = __float2bfloat16(v1);
        ochi[base + lane]      = h0;
        ochi[base + lane + 32] = h1;
        oclo[base + lane]      = __float2bfloat16(v0 - __bfloat162float(h0));
        oclo[base + lane + 32] = __float2bfloat16(v1 - __bfloat162float(h1));
    }
}

// ---------------------------------------------------------------------------

extern "C" void kernel_launch(void* const* d_in, const int* in_sizes, int n_in,
                              void* d_out, int out_size)
{
    const float* q  = (const float*)d_in[0];
    const float* k  = (const float*)d_in[1];
    const float* v  = (const float*)d_in[2];
    const float* Wq = (const float*)d_in[3];
    const float* bq = (const float*)d_in[4];
    const float* Wk = (const float*)d_in[5];
    const float* bk = (const float*)d_in[6];
    const float* Wv = (const float*)d_in[7];
    const float* bv = (const float*)d_in[8];
    const float* Wf = (const float*)d_in[9];
    const float* bf = (const float*)d_in[10];
    float* out = (float*)d_out;

    float *qh, *kh, *vh;
    __nv_bfloat16 *qhi, *qlo, *khi, *klo, *vhi, *vlo, *ochi, *oclo;
    __nv_bfloat16 *wqhi, *wqlo, *wkhi, *wklo, *wvhi, *wvlo, *wfhi, *wflo;
    cudaGetSymbolAddress((void**)&qh, g_qh);
    cudaGetSymbolAddress((void**)&kh, g_kh);
    cudaGetSymbolAddress((void**)&vh, g_vh);
    cudaGetSymbolAddress((void**)&qhi, g_qhi);   cudaGetSymbolAddress((void**)&qlo, g_qlo);
    cudaGetSymbolAddress((void**)&khi, g_khi);   cudaGetSymbolAddress((void**)&klo, g_klo);
    cudaGetSymbolAddress((void**)&vhi, g_vhi);   cudaGetSymbolAddress((void**)&vlo, g_vlo);
    cudaGetSymbolAddress((void**)&ochi, g_ochi); cudaGetSymbolAddress((void**)&oclo, g_oclo);
    cudaGetSymbolAddress((void**)&wqhi, g_wqhi); cudaGetSymbolAddress((void**)&wqlo, g_wqlo);
    cudaGetSymbolAddress((void**)&wkhi, g_wkhi); cudaGetSymbolAddress((void**)&wklo, g_wklo);
    cudaGetSymbolAddress((void**)&wvhi, g_wvhi); cudaGetSymbolAddress((void**)&wvlo, g_wvlo);
    cudaGetSymbolAddress((void**)&wfhi, g_wfhi); cudaGetSymbolAddress((void**)&wflo, g_wflo);

    // split fp32 inputs into bf16 hi/lo
    split_fp32<<<NE/4/256, 256>>>(q, qhi, qlo, NE/4);
    split_fp32<<<NE/4/256, 256>>>(k, khi, klo, NE/4);
    split_fp32<<<NE/4/256, 256>>>(v, vhi, vlo, NE/4);
    split_fp32<<<NW/4/256, 256>>>(Wq, wqhi, wqlo, NW/4);
    split_fp32<<<NW/4/256, 256>>>(Wk, wkhi, wklo, NW/4);
    split_fp32<<<NW/4/256, 256>>>(Wv, wvhi, wvlo, NW/4);
    split_fp32<<<NW/4/256, 256>>>(Wf, wfhi, wflo, NW/4);

    const int gemm_smem = 2 * STAGE_;   // 81920
    cudaFuncSetAttribute(gemm_mma, cudaFuncAttributeMaxDynamicSharedMemorySize, gemm_smem);

    dim3 gg(DM_/128, M_/128);   // (8, 64) = 512 CTAs
    gemm_mma<<<gg, 256, gemm_smem>>>(qhi, qlo, wqhi, wqlo, bq, qh, 1);
    gemm_mma<<<gg, 256, gemm_smem>>>(khi, klo, wkhi, wklo, bk, kh, 1);
    gemm_mma<<<gg, 256, gemm_smem>>>(vhi, vlo, wvhi, wvlo, bv, vh, 1);

    int attn_smem = (64*65*2 + 32*64 + 32*64) * (int)sizeof(float);  // 49664
    cudaFuncSetAttribute(attn_kernel, cudaFuncAttributeMaxDynamicSharedMemorySize, attn_smem);
    attn_kernel<<<dim3(S_/32, B_*H_), 256, attn_smem>>>(qh, kh, vh, ochi, oclo);

    gemm_mma<<<gg, 256, gemm_smem>>>(ochi, oclo, wfhi, wflo, bf, out, 0);
}